// round 1
// baseline (speedup 1.0000x reference)
#include <cuda_runtime.h>
#include <cstdint>

// ProgressiveBandHashGrid: multi-resolution hash grid encoding (Instant-NGP style)
// x:     [N, 3]  float32  (d_in[0], N*3 elements)
// table: [16, 2^19, 2] float32 (d_in[1])
// mask:  [32] float32 (d_in[2])
// out:   [N, 32] float32
//
// Levels whose mask entries are all zero are skipped entirely (0 * finite = 0).
// Resolutions replicate the reference's fp64 computation:
//   s = exp((ln 2048 - ln 16)/15), res[lv] = floor(16 * s^lv) + 1
// lv : 17 23 31 43 59 81 112 154 213 295 407 562 777 1073 1483 2049
// dense iff res^3 <= 2^19  -> lv 0..4 dense, lv >= 5 hashed.

#define THREADS 256
#define TILE_STRIDE 33   // 32 feats + 1 pad -> conflict-free smem transpose
#define TBITS 19
#define TSIZE (1u << TBITS)

__global__ void __launch_bounds__(THREADS)
hashgrid_kernel(const float* __restrict__ xin,
                const float* __restrict__ table,
                const float* __restrict__ mask,
                float* __restrict__ out,
                int n)
{
    __shared__ float tile[THREADS * TILE_STRIDE];
    const int tid = threadIdx.x;
    const int p = blockIdx.x * THREADS + tid;
    const bool valid = (p < n);

    float px = 0.f, py = 0.f, pz = 0.f;
    if (valid) {
        px = xin[3 * p + 0];
        py = xin[3 * p + 1];
        pz = xin[3 * p + 2];
    }

    const int RES[16] = {17, 23, 31, 43, 59, 81, 112, 154,
                         213, 295, 407, 562, 777, 1073, 1483, 2049};

#pragma unroll
    for (int lv = 0; lv < 16; lv++) {
        const int res = RES[lv];
        const long long r3 = (long long)res * res * res;
        const bool dense = (r3 <= (long long)TSIZE);   // compile-time per unrolled lv

        const float m0 = __ldg(mask + 2 * lv);
        const float m1 = __ldg(mask + 2 * lv + 1);
        float f0 = 0.f, f1 = 0.f;

        if ((m0 != 0.f || m1 != 0.f) && valid) {
            const float2* __restrict__ tbl =
                reinterpret_cast<const float2*>(table) + (size_t)lv * TSIZE;

            const float scale = (float)(res - 1);
            float fx = px * scale, fy = py * scale, fz = pz * scale;
            int cx = __float2int_rd(fx); cx = max(0, min(cx, res - 2));
            int cy = __float2int_rd(fy); cy = max(0, min(cy, res - 2));
            int cz = __float2int_rd(fz); cz = max(0, min(cz, res - 2));
            const float wx = fx - (float)cx;
            const float wy = fy - (float)cy;
            const float wz = fz - (float)cz;

            uint32_t i000, i100, i010, i110, i001, i101, i011, i111;
            if (dense) {
                const uint32_t sy = (uint32_t)res;
                const uint32_t sz = (uint32_t)(res * res);
                const uint32_t base = (uint32_t)(cx + res * (cy + res * cz));
                i000 = base;            i100 = base + 1u;
                i010 = base + sy;       i110 = base + sy + 1u;
                i001 = base + sz;       i101 = base + sz + 1u;
                i011 = base + sy + sz;  i111 = base + sy + sz + 1u;
            } else {
                const uint32_t P1 = 2654435761u, P2 = 805459861u;
                const uint32_t M = TSIZE - 1u;
                const uint32_t hx0 = (uint32_t)cx,       hx1 = hx0 + 1u;
                const uint32_t hy0 = (uint32_t)cy * P1,  hy1 = hy0 + P1;
                const uint32_t hz0 = (uint32_t)cz * P2,  hz1 = hz0 + P2;
                i000 = (hx0 ^ hy0 ^ hz0) & M;  i100 = (hx1 ^ hy0 ^ hz0) & M;
                i010 = (hx0 ^ hy1 ^ hz0) & M;  i110 = (hx1 ^ hy1 ^ hz0) & M;
                i001 = (hx0 ^ hy0 ^ hz1) & M;  i101 = (hx1 ^ hy0 ^ hz1) & M;
                i011 = (hx0 ^ hy1 ^ hz1) & M;  i111 = (hx1 ^ hy1 ^ hz1) & M;
            }

            const float2 v000 = __ldg(tbl + i000);
            const float2 v100 = __ldg(tbl + i100);
            const float2 v010 = __ldg(tbl + i010);
            const float2 v110 = __ldg(tbl + i110);
            const float2 v001 = __ldg(tbl + i001);
            const float2 v101 = __ldg(tbl + i101);
            const float2 v011 = __ldg(tbl + i011);
            const float2 v111 = __ldg(tbl + i111);

            const float ux = 1.f - wx, uy = 1.f - wy, uz = 1.f - wz;
            const float y0z0 = uy * uz, y1z0 = wy * uz;
            const float y0z1 = uy * wz, y1z1 = wy * wz;
            const float w000 = ux * y0z0, w100 = wx * y0z0;
            const float w010 = ux * y1z0, w110 = wx * y1z0;
            const float w001 = ux * y0z1, w101 = wx * y0z1;
            const float w011 = ux * y1z1, w111 = wx * y1z1;

            f0 = v000.x * w000;             f1 = v000.y * w000;
            f0 = fmaf(v100.x, w100, f0);    f1 = fmaf(v100.y, w100, f1);
            f0 = fmaf(v010.x, w010, f0);    f1 = fmaf(v010.y, w010, f1);
            f0 = fmaf(v110.x, w110, f0);    f1 = fmaf(v110.y, w110, f1);
            f0 = fmaf(v001.x, w001, f0);    f1 = fmaf(v001.y, w001, f1);
            f0 = fmaf(v101.x, w101, f0);    f1 = fmaf(v101.y, w101, f1);
            f0 = fmaf(v011.x, w011, f0);    f1 = fmaf(v011.y, w011, f1);
            f0 = fmaf(v111.x, w111, f0);    f1 = fmaf(v111.y, w111, f1);
            f0 *= m0;
            f1 *= m1;
        }
        tile[tid * TILE_STRIDE + 2 * lv]     = f0;
        tile[tid * TILE_STRIDE + 2 * lv + 1] = f1;
    }

    __syncthreads();

    // Coalesced streaming stores: block tile is 256 points x 32 feats = 8192 floats,
    // contiguous in gmem. float4 per lane, evict-first so output doesn't thrash L2.
    const size_t base_out = (size_t)blockIdx.x * THREADS * 32;
    const size_t lim = (size_t)n * 32;
#pragma unroll
    for (int k = 0; k < 8; k++) {
        const int e = k * 1024 + tid * 4;  // element within block tile [0, 8192)
        const int pp = e >> 5;
        const int f = e & 31;
        float4 v;
        v.x = tile[pp * TILE_STRIDE + f + 0];
        v.y = tile[pp * TILE_STRIDE + f + 1];
        v.z = tile[pp * TILE_STRIDE + f + 2];
        v.w = tile[pp * TILE_STRIDE + f + 3];
        const size_t gi = base_out + (size_t)e;
        if (gi < lim) {
            __stcs(reinterpret_cast<float4*>(out + gi), v);
        }
    }
}

extern "C" void kernel_launch(void* const* d_in, const int* in_sizes, int n_in,
                              void* d_out, int out_size) {
    const float* x     = (const float*)d_in[0];
    const float* table = (const float*)d_in[1];
    const float* mask  = (const float*)d_in[2];
    float* out = (float*)d_out;
    const int n = in_sizes[0] / 3;
    const int blocks = (n + THREADS - 1) / THREADS;
    hashgrid_kernel<<<blocks, THREADS>>>(x, table, mask, out, n);
}

// round 2
// speedup vs baseline: 1.7199x; 1.7199x over previous
#include <cuda_runtime.h>
#include <cstdint>

// ProgressiveBandHashGrid — thread-per-(point, level) mapping for latency hiding.
// x:     [N, 3]  float32
// table: [16, 2^19, 2] float32
// mask:  [32] float32   (level lv active iff mask[2lv] or mask[2lv+1] != 0)
// out:   [N, 32] float32
//
// Resolutions (replicating reference fp64): 17 23 31 43 59 81 112 154 213 295
// 407 562 777 1073 1483 2049. dense iff res^3 <= 2^19 -> lv 0..4 dense.

#define THREADS 256
#define PTS 32           // points per block (one warp-lane each)
#define NWARPS 8
#define TILE_STRIDE 33   // 32 feats + 1 pad
#define TBITS 19
#define TSIZE (1u << TBITS)

__constant__ int c_res[16]  = {17, 23, 31, 43, 59, 81, 112, 154,
                               213, 295, 407, 562, 777, 1073, 1483, 2049};
__constant__ int c_res2[16] = {289, 529, 961, 1849, 3481, 6561, 12544, 23716,
                               45369, 87025, 165649, 315844, 603729, 1151329,
                               2199289, 4198401};
__constant__ int c_dense[16] = {1, 1, 1, 1, 1, 0, 0, 0,
                                0, 0, 0, 0, 0, 0, 0, 0};

__global__ void __launch_bounds__(THREADS)
hashgrid_kernel(const float* __restrict__ xin,
                const float* __restrict__ table,
                const float* __restrict__ mask,
                float* __restrict__ out,
                int n)
{
    __shared__ float sx[PTS * 3];
    __shared__ float tile[PTS * TILE_STRIDE];
    __shared__ int s_act[17];          // [0]=count, [1..16]=active level ids

    const int tid = threadIdx.x;
    const size_t p0 = (size_t)blockIdx.x * PTS;

    // Load this block's 32 points' coords (96 floats, coalesced).
    if (tid < PTS * 3) {
        const size_t gi = p0 * 3 + tid;
        sx[tid] = (gi < (size_t)n * 3) ? xin[gi] : 0.f;
    }
    // Compact active level list from the mask (runtime-data driven, general).
    if (tid == 0) {
        int c = 0;
#pragma unroll
        for (int l = 0; l < 16; l++) {
            if (__ldg(mask + 2 * l) != 0.f || __ldg(mask + 2 * l + 1) != 0.f)
                s_act[1 + c++] = l;
        }
        s_act[0] = c;
    }
    // Zero the output tile (inactive levels stay zero).
#pragma unroll
    for (int i = tid; i < PTS * TILE_STRIDE; i += THREADS) tile[i] = 0.f;
    __syncthreads();

    const int warp = tid >> 5;
    const int lane = tid & 31;
    const int nact = s_act[0];
    const bool valid = (p0 + (size_t)lane) < (size_t)n;

    const float px = sx[lane * 3 + 0];
    const float py = sx[lane * 3 + 1];
    const float pz = sx[lane * 3 + 2];

    for (int a = warp; a < nact; a += NWARPS) {
        const int lv = s_act[1 + a];
        if (!valid) continue;

        const int res = c_res[lv];
        const float2* __restrict__ tbl =
            reinterpret_cast<const float2*>(table) + (size_t)lv * TSIZE;

        const float scale = (float)(res - 1);
        const float fx = px * scale, fy = py * scale, fz = pz * scale;
        int cx = __float2int_rd(fx); cx = max(0, min(cx, res - 2));
        int cy = __float2int_rd(fy); cy = max(0, min(cy, res - 2));
        int cz = __float2int_rd(fz); cz = max(0, min(cz, res - 2));
        const float wx = fx - (float)cx;
        const float wy = fy - (float)cy;
        const float wz = fz - (float)cz;

        uint32_t i000, i100, i010, i110, i001, i101, i011, i111;
        if (c_dense[lv]) {                       // warp-uniform branch
            const uint32_t sy = (uint32_t)res;
            const uint32_t sz = (uint32_t)c_res2[lv];
            const uint32_t base = (uint32_t)cx + sy * (uint32_t)cy + sz * (uint32_t)cz;
            i000 = base;            i100 = base + 1u;
            i010 = base + sy;       i110 = base + sy + 1u;
            i001 = base + sz;       i101 = base + sz + 1u;
            i011 = base + sy + sz;  i111 = base + sy + sz + 1u;
        } else {
            const uint32_t P1 = 2654435761u, P2 = 805459861u;
            const uint32_t M = TSIZE - 1u;
            const uint32_t hx0 = (uint32_t)cx,      hx1 = hx0 + 1u;
            const uint32_t hy0 = (uint32_t)cy * P1, hy1 = hy0 + P1;
            const uint32_t hz0 = (uint32_t)cz * P2, hz1 = hz0 + P2;
            i000 = (hx0 ^ hy0 ^ hz0) & M;  i100 = (hx1 ^ hy0 ^ hz0) & M;
            i010 = (hx0 ^ hy1 ^ hz0) & M;  i110 = (hx1 ^ hy1 ^ hz0) & M;
            i001 = (hx0 ^ hy0 ^ hz1) & M;  i101 = (hx1 ^ hy0 ^ hz1) & M;
            i011 = (hx0 ^ hy1 ^ hz1) & M;  i111 = (hx1 ^ hy1 ^ hz1) & M;
        }

        const float2 v000 = __ldg(tbl + i000);
        const float2 v100 = __ldg(tbl + i100);
        const float2 v010 = __ldg(tbl + i010);
        const float2 v110 = __ldg(tbl + i110);
        const float2 v001 = __ldg(tbl + i001);
        const float2 v101 = __ldg(tbl + i101);
        const float2 v011 = __ldg(tbl + i011);
        const float2 v111 = __ldg(tbl + i111);

        const float ux = 1.f - wx, uy = 1.f - wy, uz = 1.f - wz;
        const float y0z0 = uy * uz, y1z0 = wy * uz;
        const float y0z1 = uy * wz, y1z1 = wy * wz;
        const float w000 = ux * y0z0, w100 = wx * y0z0;
        const float w010 = ux * y1z0, w110 = wx * y1z0;
        const float w001 = ux * y0z1, w101 = wx * y0z1;
        const float w011 = ux * y1z1, w111 = wx * y1z1;

        float f0 = v000.x * w000, f1 = v000.y * w000;
        f0 = fmaf(v100.x, w100, f0);  f1 = fmaf(v100.y, w100, f1);
        f0 = fmaf(v010.x, w010, f0);  f1 = fmaf(v010.y, w010, f1);
        f0 = fmaf(v110.x, w110, f0);  f1 = fmaf(v110.y, w110, f1);
        f0 = fmaf(v001.x, w001, f0);  f1 = fmaf(v001.y, w001, f1);
        f0 = fmaf(v101.x, w101, f0);  f1 = fmaf(v101.y, w101, f1);
        f0 = fmaf(v011.x, w011, f0);  f1 = fmaf(v011.y, w011, f1);
        f0 = fmaf(v111.x, w111, f0);  f1 = fmaf(v111.y, w111, f1);

        f0 *= __ldg(mask + 2 * lv);
        f1 *= __ldg(mask + 2 * lv + 1);

        tile[lane * TILE_STRIDE + 2 * lv]     = f0;   // distinct lv per warp: no race
        tile[lane * TILE_STRIDE + 2 * lv + 1] = f1;
    }

    __syncthreads();

    // Coalesced streaming store: 32 points x 32 feats = 1024 floats = 256 x float4.
    const size_t base_out = p0 * 32;
    const size_t lim = (size_t)n * 32;
    const int e = tid * 4;              // element within block tile [0, 1024)
    const int pp = e >> 5;
    const int f = e & 31;
    float4 v;
    v.x = tile[pp * TILE_STRIDE + f + 0];
    v.y = tile[pp * TILE_STRIDE + f + 1];
    v.z = tile[pp * TILE_STRIDE + f + 2];
    v.w = tile[pp * TILE_STRIDE + f + 3];
    const size_t gi = base_out + (size_t)e;
    if (gi < lim) {
        __stcs(reinterpret_cast<float4*>(out + gi), v);
    }
}

extern "C" void kernel_launch(void* const* d_in, const int* in_sizes, int n_in,
                              void* d_out, int out_size) {
    const float* x     = (const float*)d_in[0];
    const float* table = (const float*)d_in[1];
    const float* mask  = (const float*)d_in[2];
    float* out = (float*)d_out;
    const int n = in_sizes[0] / 3;
    const int blocks = (n + PTS - 1) / PTS;
    hashgrid_kernel<<<blocks, THREADS>>>(x, table, mask, out, n);
}

// round 3
// speedup vs baseline: 2.0031x; 1.1646x over previous
#include <cuda_runtime.h>
#include <cstdint>

// ProgressiveBandHashGrid — thread-per-(point, level) + x-corner pair fusion.
// x:     [N, 3]  float32
// table: [16, 2^19, 2] float32
// mask:  [32] float32   (level lv active iff mask[2lv] or mask[2lv+1] != 0)
// out:   [N, 32] float32
//
// Resolutions (reference fp64): 17 23 31 43 59 81 112 154 213 295 407 562 777
// 1073 1483 2049. dense iff res^3 <= 2^19 -> lv 0..4 dense.
//
// Wavefront reduction: table[T,2] reinterpreted as float4[T/2]; x-corner pairs
// whose indices satisfy (i0^i1)==1 (dense even-base, hashed even-cx) load as a
// single LDG.128 -> 1 L1 wavefront instead of 2.

#define THREADS 256
#define PTS 32           // points per block (one warp-lane each)
#define NWARPS 8
#define TILE_STRIDE 33   // 32 feats + 1 pad
#define TBITS 19
#define TSIZE (1u << TBITS)

__constant__ int c_res[16]  = {17, 23, 31, 43, 59, 81, 112, 154,
                               213, 295, 407, 562, 777, 1073, 1483, 2049};
__constant__ int c_res2[16] = {289, 529, 961, 1849, 3481, 6561, 12544, 23716,
                               45369, 87025, 165649, 315844, 603729, 1151329,
                               2199289, 4198401};
__constant__ int c_dense[16] = {1, 1, 1, 1, 1, 0, 0, 0,
                                0, 0, 0, 0, 0, 0, 0, 0};

// Load the x-corner pair (i0, i1) for one (y,z) corner. If indices are an
// aligned adjacent pair, use one 16B load; else two 8B loads.
__device__ __forceinline__ void load_pair(const float2* __restrict__ tbl,
                                          uint32_t i0, uint32_t i1,
                                          float2& v0, float2& v1)
{
    if ((i0 ^ i1) == 1u) {
        const float4 q = __ldg(reinterpret_cast<const float4*>(tbl) + (i0 >> 1));
        if (i0 & 1u) { v0.x = q.z; v0.y = q.w; v1.x = q.x; v1.y = q.y; }
        else         { v0.x = q.x; v0.y = q.y; v1.x = q.z; v1.y = q.w; }
    } else {
        v0 = __ldg(tbl + i0);
        v1 = __ldg(tbl + i1);
    }
}

__global__ void __launch_bounds__(THREADS)
hashgrid_kernel(const float* __restrict__ xin,
                const float* __restrict__ table,
                const float* __restrict__ mask,
                float* __restrict__ out,
                int n)
{
    __shared__ float sx[PTS * 3];
    __shared__ float tile[PTS * TILE_STRIDE];
    __shared__ int s_act[17];          // [0]=count, [1..16]=active level ids

    const int tid = threadIdx.x;
    const size_t p0 = (size_t)blockIdx.x * PTS;

    if (tid < PTS * 3) {
        const size_t gi = p0 * 3 + tid;
        sx[tid] = (gi < (size_t)n * 3) ? xin[gi] : 0.f;
    }
    if (tid == 0) {
        int c = 0;
#pragma unroll
        for (int l = 0; l < 16; l++) {
            if (__ldg(mask + 2 * l) != 0.f || __ldg(mask + 2 * l + 1) != 0.f)
                s_act[1 + c++] = l;
        }
        s_act[0] = c;
    }
#pragma unroll
    for (int i = tid; i < PTS * TILE_STRIDE; i += THREADS) tile[i] = 0.f;
    __syncthreads();

    const int warp = tid >> 5;
    const int lane = tid & 31;
    const int nact = s_act[0];
    const bool valid = (p0 + (size_t)lane) < (size_t)n;

    const float px = sx[lane * 3 + 0];
    const float py = sx[lane * 3 + 1];
    const float pz = sx[lane * 3 + 2];

    for (int a = warp; a < nact; a += NWARPS) {
        const int lv = s_act[1 + a];
        if (!valid) continue;

        const int res = c_res[lv];
        const float2* __restrict__ tbl =
            reinterpret_cast<const float2*>(table) + (size_t)lv * TSIZE;

        const float scale = (float)(res - 1);
        const float fx = px * scale, fy = py * scale, fz = pz * scale;
        int cx = __float2int_rd(fx); cx = max(0, min(cx, res - 2));
        int cy = __float2int_rd(fy); cy = max(0, min(cy, res - 2));
        int cz = __float2int_rd(fz); cz = max(0, min(cz, res - 2));
        const float wx = fx - (float)cx;
        const float wy = fy - (float)cy;
        const float wz = fz - (float)cz;

        uint32_t i000, i100, i010, i110, i001, i101, i011, i111;
        if (c_dense[lv]) {                       // warp-uniform branch
            const uint32_t sy = (uint32_t)res;
            const uint32_t sz = (uint32_t)c_res2[lv];
            const uint32_t base = (uint32_t)cx + sy * (uint32_t)cy + sz * (uint32_t)cz;
            i000 = base;            i100 = base + 1u;
            i010 = base + sy;       i110 = base + sy + 1u;
            i001 = base + sz;       i101 = base + sz + 1u;
            i011 = base + sy + sz;  i111 = base + sy + sz + 1u;
        } else {
            const uint32_t P1 = 2654435761u, P2 = 805459861u;
            const uint32_t M = TSIZE - 1u;
            const uint32_t hx0 = (uint32_t)cx,      hx1 = hx0 + 1u;
            const uint32_t hy0 = (uint32_t)cy * P1, hy1 = hy0 + P1;
            const uint32_t hz0 = (uint32_t)cz * P2, hz1 = hz0 + P2;
            i000 = (hx0 ^ hy0 ^ hz0) & M;  i100 = (hx1 ^ hy0 ^ hz0) & M;
            i010 = (hx0 ^ hy1 ^ hz0) & M;  i110 = (hx1 ^ hy1 ^ hz0) & M;
            i001 = (hx0 ^ hy0 ^ hz1) & M;  i101 = (hx1 ^ hy0 ^ hz1) & M;
            i011 = (hx0 ^ hy1 ^ hz1) & M;  i111 = (hx1 ^ hy1 ^ hz1) & M;
        }

        float2 v000, v100, v010, v110, v001, v101, v011, v111;
        load_pair(tbl, i000, i100, v000, v100);
        load_pair(tbl, i010, i110, v010, v110);
        load_pair(tbl, i001, i101, v001, v101);
        load_pair(tbl, i011, i111, v011, v111);

        const float ux = 1.f - wx, uy = 1.f - wy, uz = 1.f - wz;
        const float y0z0 = uy * uz, y1z0 = wy * uz;
        const float y0z1 = uy * wz, y1z1 = wy * wz;
        const float w000 = ux * y0z0, w100 = wx * y0z0;
        const float w010 = ux * y1z0, w110 = wx * y1z0;
        const float w001 = ux * y0z1, w101 = wx * y0z1;
        const float w011 = ux * y1z1, w111 = wx * y1z1;

        float f0 = v000.x * w000, f1 = v000.y * w000;
        f0 = fmaf(v100.x, w100, f0);  f1 = fmaf(v100.y, w100, f1);
        f0 = fmaf(v010.x, w010, f0);  f1 = fmaf(v010.y, w010, f1);
        f0 = fmaf(v110.x, w110, f0);  f1 = fmaf(v110.y, w110, f1);
        f0 = fmaf(v001.x, w001, f0);  f1 = fmaf(v001.y, w001, f1);
        f0 = fmaf(v101.x, w101, f0);  f1 = fmaf(v101.y, w101, f1);
        f0 = fmaf(v011.x, w011, f0);  f1 = fmaf(v011.y, w011, f1);
        f0 = fmaf(v111.x, w111, f0);  f1 = fmaf(v111.y, w111, f1);

        f0 *= __ldg(mask + 2 * lv);
        f1 *= __ldg(mask + 2 * lv + 1);

        tile[lane * TILE_STRIDE + 2 * lv]     = f0;   // distinct lv per warp: no race
        tile[lane * TILE_STRIDE + 2 * lv + 1] = f1;
    }

    __syncthreads();

    // Coalesced streaming store: 32 points x 32 feats = 1024 floats = 256 x float4.
    const size_t base_out = p0 * 32;
    const size_t lim = (size_t)n * 32;
    const int e = tid * 4;
    const int pp = e >> 5;
    const int f = e & 31;
    float4 v;
    v.x = tile[pp * TILE_STRIDE + f + 0];
    v.y = tile[pp * TILE_STRIDE + f + 1];
    v.z = tile[pp * TILE_STRIDE + f + 2];
    v.w = tile[pp * TILE_STRIDE + f + 3];
    const size_t gi = base_out + (size_t)e;
    if (gi < lim) {
        __stcs(reinterpret_cast<float4*>(out + gi), v);
    }
}

extern "C" void kernel_launch(void* const* d_in, const int* in_sizes, int n_in,
                              void* d_out, int out_size) {
    const float* x     = (const float*)d_in[0];
    const float* table = (const float*)d_in[1];
    const float* mask  = (const float*)d_in[2];
    float* out = (float*)d_out;
    const int n = in_sizes[0] / 3;
    const int blocks = (n + PTS - 1) / PTS;
    hashgrid_kernel<<<blocks, THREADS>>>(x, table, mask, out, n);
}